// round 4
// baseline (speedup 1.0000x reference)
#include <cuda_runtime.h>
#include <cstdint>

// AttentionLayer: B=2048, N=64, D=256, H=16
//   m_i[h]  = sum_d members[b,i,d]*item[b,d]*W1[d,h]
//   s[h]    = sum_i m_i[h] ; pre = 64*m_i - s + b1 ; relu ; logit = relu@W2 + b2
//   out[b,i] = softmax_i(logit)
//
// R4: block = 4 warps = 1 batch. Warp owns 4 heads (h = 4*wid + lane>>3),
// lane owns 32 d-values (quads 8t + (lane&7)) -> wreg = 32 regs.
// Cooperative cp.async ring (4 slots x 2 rows, 1 instr/thread/slot).
// launch_bounds(128,5) -> 20 warps/SM.

constexpr int Bb = 2048;
constexpr int Nn = 64;
constexpr int Dd = 256;
constexpr int Hh = 16;
constexpr int THREADS = 128;
constexpr int RING = 4;                // slots of 2 rows each

#define FMA2(acc, a, w)  asm("fma.rn.f32x2 %0, %1, %2, %0;" : "+l"(acc) : "l"(a), "l"(w))
#define ADD2(d, a, b_)   asm("add.rn.f32x2 %0, %1, %2;" : "=l"(d) : "l"(a), "l"(b_))
#define PACK2(d, lo, hi) asm("mov.b64 %0, {%1, %2};" : "=l"(d) : "f"(lo), "f"(hi))
#define UNPACK2(lo, hi, v) asm("mov.b64 {%0, %1}, %2;" : "=f"(lo), "=f"(hi) : "l"(v))

__device__ __forceinline__ uint32_t smem_u32(const void* p) {
    uint32_t a;
    asm("{ .reg .u64 t; cvta.to.shared.u64 t, %1; cvt.u32.u64 %0, t; }"
        : "=r"(a) : "l"(p));
    return a;
}
__device__ __forceinline__ void cp_async16(uint32_t dst, const void* src) {
    asm volatile("cp.async.cg.shared.global [%0], [%1], 16;" :: "r"(dst), "l"(src));
}
__device__ __forceinline__ void cp_commit() {
    asm volatile("cp.async.commit_group;" ::: "memory");
}
__device__ __forceinline__ void cp_wait2() {
    asm volatile("cp.async.wait_group %0;" :: "n"(RING - 2) : "memory");
}

__global__ __launch_bounds__(THREADS, 5)
void attn_kernel(const float* __restrict__ members,
                 const float* __restrict__ item,
                 const float* __restrict__ W1,
                 const float* __restrict__ b1,
                 const float* __restrict__ W2,
                 const float* __restrict__ b2,
                 float* __restrict__ out)
{
    __shared__ float4 ring[RING][2][Dd / 4];   // 8 KB: 4 slots x 2 rows x 1 KB
    __shared__ float  mS[Nn * (Hh + 1)];       // 4.35 KB, stride 17
    __shared__ float  sS[Hh];
    __shared__ float  red[2][2];               // [max|sum][warp parity]

    const int tid  = threadIdx.x;
    const int wid  = tid >> 5;
    const int lane = tid & 31;
    const int h    = 4 * wid + (lane >> 3);    // head owned by this lane
    const int r8   = lane & 7;                 // d-eighth owned (quads 8t + r8)
    const int b    = blockIdx.x;

    const float4* grow = (const float4*)(members + (size_t)b * Nn * Dd);
    const uint32_t ringBase = smem_u32(&ring[0][0][0]);
    // cooperative fill: thread covers one float4 of the 2-row slot
    const int fr  = tid >> 6;                  // which row of the slot (0/1)
    const int fc  = tid & 63;                  // float4 index within row
    const uint32_t fillOff = (uint32_t)tid * 16;

    // ---- prologue: slots 0..2 (rows 0..5) in flight ----
    #pragma unroll
    for (int it = 0; it < RING - 1; it++) {
        cp_async16(ringBase + it * 2048 + fillOff,
                   grow + (2 * it + fr) * (Dd / 4) + fc);
        cp_commit();
    }

    // ---- register weights: w[d] = W1[d][h]*item[b][d], lane's 32 d's ----
    const float* itG = item + (size_t)b * Dd;
    unsigned long long wreg[16];
    #pragma unroll
    for (int t = 0; t < 8; t++) {
        const int d0 = (8 * t + r8) * 4;
        float w0 = __ldg(&W1[(d0 + 0) * Hh + h]) * __ldg(&itG[d0 + 0]);
        float w1 = __ldg(&W1[(d0 + 1) * Hh + h]) * __ldg(&itG[d0 + 1]);
        float w2 = __ldg(&W1[(d0 + 2) * Hh + h]) * __ldg(&itG[d0 + 2]);
        float w3 = __ldg(&W1[(d0 + 3) * Hh + h]) * __ldg(&itG[d0 + 3]);
        PACK2(wreg[2 * t],     w0, w1);
        PACK2(wreg[2 * t + 1], w2, w3);
    }

    // ---- main loop: 32 iterations x 2 rows ----
    float s_h = 0.f;
    for (int i = 0; i < Nn / 2; i++) {
        cp_wait2();                 // slot i landed (<=2 newer groups pending)
        __syncthreads();            // cross-warp visibility + slot (i-1)&3 free

        if (i + RING - 1 < Nn / 2) {
            const int it = i + RING - 1;
            cp_async16(ringBase + (it & (RING - 1)) * 2048 + fillOff,
                       grow + (2 * it + fr) * (Dd / 4) + fc);
        }
        cp_commit();                // always commit: wait arithmetic stays exact

        const ulonglong2* ra = (const ulonglong2*)&ring[i & (RING - 1)][0][0];
        const ulonglong2* rb = ra + 64;    // second row of slot

        unsigned long long aA0 = 0ull, aA1 = 0ull, aB0 = 0ull, aB1 = 0ull;
        #pragma unroll
        for (int t = 0; t < 8; t++) {
            ulonglong2 va = ra[8 * t + r8];    // 8 distinct 16B addrs, 128B contig
            ulonglong2 vb = rb[8 * t + r8];    // 4-way broadcast, conflict-free
            FMA2(aA0, va.x, wreg[2 * t]);
            FMA2(aA1, va.y, wreg[2 * t + 1]);
            FMA2(aB0, vb.x, wreg[2 * t]);
            FMA2(aB1, vb.y, wreg[2 * t + 1]);
        }
        unsigned long long tA, tB;
        ADD2(tA, aA0, aA1);
        ADD2(tB, aB0, aB1);
        float la, ha, lb, hb;
        UNPACK2(la, ha, tA);
        UNPACK2(lb, hb, tB);
        float mA = la + ha;
        float mB = lb + hb;
        // reduce across the 8 lanes sharing this head (xor 1,2,4)
        #pragma unroll
        for (int o = 1; o <= 4; o <<= 1) {
            mA += __shfl_xor_sync(0xffffffffu, mA, o);
            mB += __shfl_xor_sync(0xffffffffu, mB, o);
        }
        s_h += mA + mB;
        if (r8 == 0) {
            mS[(2 * i)     * (Hh + 1) + h] = mA;
            mS[(2 * i + 1) * (Hh + 1) + h] = mB;
        }
    }

    if (r8 == 0) sS[h] = s_h;
    __syncthreads();                // mS + sS complete across all 4 warps

    // ---- epilogue: warps 0-1 compute logits (1 row/lane), all warps barrier ----
    const int p   = wid & 1;
    const int row = p * 32 + lane;
    float logit = 0.f, e = 0.f;
    if (wid < 2) {
        logit = __ldg(b2);
        #pragma unroll
        for (int hh = 0; hh < 16; hh++) {
            const float c   = __ldg(&b1[hh]) - sS[hh];
            const float w2r = __ldg(&W2[hh]);
            const float pre = 64.f * mS[row * (Hh + 1) + hh] + c;
            logit += fmaxf(pre, 0.f) * w2r;
        }
        float mx = logit;
        #pragma unroll
        for (int o = 16; o >= 1; o >>= 1)
            mx = fmaxf(mx, __shfl_xor_sync(0xffffffffu, mx, o));
        if (lane == 0) red[0][p] = mx;
    }
    __syncthreads();
    if (wid < 2) {
        const float mxAll = fmaxf(red[0][0], red[0][1]);
        e = __expf(logit - mxAll);
        float sm = e;
        #pragma unroll
        for (int o = 16; o >= 1; o >>= 1)
            sm += __shfl_xor_sync(0xffffffffu, sm, o);
        if (lane == 0) red[1][p] = sm;
    }
    __syncthreads();
    if (wid < 2) {
        const float inv = 1.0f / (red[1][0] + red[1][1]);
        out[(size_t)b * Nn + row] = e * inv;
    }
}

extern "C" void kernel_launch(void* const* d_in, const int* in_sizes, int n_in,
                              void* d_out, int out_size)
{
    attn_kernel<<<Bb, THREADS>>>(
        (const float*)d_in[0],   // members_embeds [2048,64,256]
        (const float*)d_in[1],   // item_embeds    [2048,256]
        (const float*)d_in[2],   // W1 [256,16]
        (const float*)d_in[3],   // b1 [16]
        (const float*)d_in[4],   // W2 [16,1]
        (const float*)d_in[5],   // b2 [1]
        (float*)d_out);          // out [2048,64]
}

// round 5
// speedup vs baseline: 1.8226x; 1.8226x over previous
#include <cuda_runtime.h>
#include <cstdint>

// AttentionLayer: B=2048, N=64, D=256, H=16
//   m_i[h]  = sum_d members[b,i,d]*item[b,d]*W1[d,h]
//   s[h]    = sum_i m_i[h] ; pre = 64*m_i - s + b1 ; relu ; logit = relu@W2 + b2
//   out[b,i] = softmax_i(logit)
//
// R5: block = 64 threads = 2 warps = 1 batch. Warp p covers heads 8p..8p+7.
// Lane owns 2 heads (h0 = 8p + 2*(lane&3)) x 32 d (quads 8t + (lane>>2)).
// Crossbar traffic halved vs R3 (16 LDS.128 per 2-row iter per warp).
// Weights register-resident (64 regs), cp.async ring 4 slots x 2 rows.

constexpr int Bb = 2048;
constexpr int Nn = 64;
constexpr int Dd = 256;
constexpr int Hh = 16;
constexpr int THREADS = 64;
constexpr int RING = 4;                // slots of 2 rows (2 KB each)
constexpr int MSTR = 18;               // mS row stride (even -> 8B-aligned STS.64)

#define FMA2(acc, a, w)  asm("fma.rn.f32x2 %0, %1, %2, %0;" : "+l"(acc) : "l"(a), "l"(w))
#define ADD2(d, a, b_)   asm("add.rn.f32x2 %0, %1, %2;" : "=l"(d) : "l"(a), "l"(b_))
#define PACK2(d, lo, hi) asm("mov.b64 %0, {%1, %2};" : "=l"(d) : "f"(lo), "f"(hi))
#define UNPACK2(lo, hi, v) asm("mov.b64 {%0, %1}, %2;" : "=f"(lo), "=f"(hi) : "l"(v))

__device__ __forceinline__ uint32_t smem_u32(const void* p) {
    uint32_t a;
    asm("{ .reg .u64 t; cvta.to.shared.u64 t, %1; cvt.u32.u64 %0, t; }"
        : "=r"(a) : "l"(p));
    return a;
}
__device__ __forceinline__ void cp_async16(uint32_t dst, const void* src) {
    asm volatile("cp.async.cg.shared.global [%0], [%1], 16;" :: "r"(dst), "l"(src));
}
__device__ __forceinline__ void cp_commit() {
    asm volatile("cp.async.commit_group;" ::: "memory");
}
__device__ __forceinline__ void cp_wait2() {
    asm volatile("cp.async.wait_group %0;" :: "n"(RING - 2) : "memory");
}

__global__ __launch_bounds__(THREADS, 8)
void attn_kernel(const float* __restrict__ members,
                 const float* __restrict__ item,
                 const float* __restrict__ W1,
                 const float* __restrict__ b1,
                 const float* __restrict__ W2,
                 const float* __restrict__ b2,
                 float* __restrict__ out)
{
    __shared__ float4 ring[RING][2][Dd / 4];   // 8 KB: 4 slots x 2 rows x 1 KB
    __shared__ float  mS[Nn * MSTR];           // 4.6 KB
    __shared__ float  sS[Hh];
    __shared__ float  red[2][2];               // [max|sum][warp]

    const int tid    = threadIdx.x;
    const int p      = tid >> 5;               // warp: heads 8p..8p+7
    const int lane   = tid & 31;
    const int hgrp   = lane & 3;               // head pair within warp
    const int dsplit = lane >> 2;              // d-eighth (quads 8t + dsplit)
    const int h0     = 8 * p + 2 * hgrp;       // lane's first head
    const int b      = blockIdx.x;

    const float4* grow = (const float4*)(members + (size_t)b * Nn * Dd);
    const uint32_t ringBase = smem_u32(&ring[0][0][0]);

    // ---- prologue: slots 0..2 (rows 0..5) in flight ----
    #pragma unroll
    for (int it = 0; it < RING - 1; it++) {
        cp_async16(ringBase + it * 2048 +        tid * 16, grow + (2 * it)     * 64 + tid);
        cp_async16(ringBase + it * 2048 + 1024 + tid * 16, grow + (2 * it + 1) * 64 + tid);
        cp_commit();
    }

    // ---- register weights: wreg[4t + 2j + par] = (W1[d,h0+j]*it[d]) pairs ----
    const float* itG = item + (size_t)b * Dd;
    unsigned long long wreg[32];
    #pragma unroll
    for (int t = 0; t < 8; t++) {
        const int d0 = (8 * t + dsplit) * 4;
        const float4 it4 = __ldg((const float4*)&itG[d0]);
        #pragma unroll
        for (int j = 0; j < 2; j++) {
            const int h = h0 + j;
            float w0 = __ldg(&W1[(d0 + 0) * Hh + h]) * it4.x;
            float w1 = __ldg(&W1[(d0 + 1) * Hh + h]) * it4.y;
            float w2 = __ldg(&W1[(d0 + 2) * Hh + h]) * it4.z;
            float w3 = __ldg(&W1[(d0 + 3) * Hh + h]) * it4.w;
            PACK2(wreg[4 * t + 2 * j],     w0, w1);
            PACK2(wreg[4 * t + 2 * j + 1], w2, w3);
        }
    }

    // ---- main loop: 32 iterations x 2 rows ----
    unsigned long long s2 = 0ull;              // packed (s_h0, s_h1)
    for (int i = 0; i < Nn / 2; i++) {
        cp_wait2();                 // own groups for slot i complete
        __syncthreads();            // all threads' fills visible; slot (i-1)&3 free

        if (i + RING - 1 < Nn / 2) {
            const int it = i + RING - 1;
            const uint32_t d0 = ringBase + (it & (RING - 1)) * 2048 + tid * 16;
            cp_async16(d0,        grow + (2 * it)     * 64 + tid);
            cp_async16(d0 + 1024, grow + (2 * it + 1) * 64 + tid);
        }
        cp_commit();                // unconditional: wait arithmetic stays exact

        const ulonglong2* rA = (const ulonglong2*)&ring[i & (RING - 1)][0][0];
        const ulonglong2* rB = rA + 64;

        unsigned long long aA0e=0, aA0o=0, aA1e=0, aA1o=0;
        unsigned long long aB0e=0, aB0o=0, aB1e=0, aB1o=0;
        #pragma unroll
        for (int t = 0; t < 8; t++) {
            const ulonglong2 va = rA[8 * t + dsplit];  // 8 distinct 16B addrs/warp
            const ulonglong2 vb = rB[8 * t + dsplit];  // 4-way bcast, conflict-free
            FMA2(aA0e, va.x, wreg[4 * t]);
            FMA2(aA0o, va.y, wreg[4 * t + 1]);
            FMA2(aA1e, va.x, wreg[4 * t + 2]);
            FMA2(aA1o, va.y, wreg[4 * t + 3]);
            FMA2(aB0e, vb.x, wreg[4 * t]);
            FMA2(aB0o, vb.y, wreg[4 * t + 1]);
            FMA2(aB1e, vb.x, wreg[4 * t + 2]);
            FMA2(aB1o, vb.y, wreg[4 * t + 3]);
        }
        ADD2(aA0e, aA0e, aA0o);  ADD2(aA1e, aA1e, aA1o);
        ADD2(aB0e, aB0e, aB0o);  ADD2(aB1e, aB1e, aB1o);
        float x, y, mA0, mA1, mB0, mB1;
        UNPACK2(x, y, aA0e); mA0 = x + y;
        UNPACK2(x, y, aA1e); mA1 = x + y;
        UNPACK2(x, y, aB0e); mB0 = x + y;
        UNPACK2(x, y, aB1e); mB1 = x + y;

        unsigned long long mmA, mmB, tmp;
        PACK2(mmA, mA0, mA1);       // (m_h0, m_h1) row A
        PACK2(mmB, mB0, mB1);       // (m_h0, m_h1) row B
        #pragma unroll
        for (int o = 4; o <= 16; o <<= 1) {    // butterfly over the 8 d-split lanes
            tmp = __shfl_xor_sync(0xffffffffu, mmA, o); ADD2(mmA, mmA, tmp);
            tmp = __shfl_xor_sync(0xffffffffu, mmB, o); ADD2(mmB, mmB, tmp);
        }
        ADD2(s2, s2, mmA);
        ADD2(s2, s2, mmB);
        if (lane < 4) {             // dsplit==0 lanes publish both heads at once
            *(unsigned long long*)&mS[(2 * i)     * MSTR + h0] = mmA;
            *(unsigned long long*)&mS[(2 * i + 1) * MSTR + h0] = mmB;
        }
    }

    if (lane < 4) *(unsigned long long*)&sS[h0] = s2;
    __syncthreads();

    // ---- epilogue: 1 row per lane (warp p -> rows 32p..32p+31) ----
    const int row = p * 32 + lane;
    float logit = __ldg(b2);
    #pragma unroll
    for (int hh = 0; hh < 16; hh++) {
        const float pre = 64.f * mS[row * MSTR + hh] + __ldg(&b1[hh]) - sS[hh];
        logit += fmaxf(pre, 0.f) * __ldg(&W2[hh]);
    }

    float mx = logit;
    #pragma unroll
    for (int o = 16; o >= 1; o >>= 1)
        mx = fmaxf(mx, __shfl_xor_sync(0xffffffffu, mx, o));
    if (lane == 0) red[0][p] = mx;
    __syncthreads();
    const float mxAll = fmaxf(red[0][0], red[0][1]);

    const float e = __expf(logit - mxAll);
    float sm = e;
    #pragma unroll
    for (int o = 16; o >= 1; o >>= 1)
        sm += __shfl_xor_sync(0xffffffffu, sm, o);
    if (lane == 0) red[1][p] = sm;
    __syncthreads();
    const float inv = 1.0f / (red[1][0] + red[1][1]);

    out[(size_t)b * Nn + row] = e * inv;
}

extern "C" void kernel_launch(void* const* d_in, const int* in_sizes, int n_in,
                              void* d_out, int out_size)
{
    attn_kernel<<<Bb, THREADS>>>(
        (const float*)d_in[0],   // members_embeds [2048,64,256]
        (const float*)d_in[1],   // item_embeds    [2048,256]
        (const float*)d_in[2],   // W1 [256,16]
        (const float*)d_in[3],   // b1 [16]
        (const float*)d_in[4],   // W2 [16,1]
        (const float*)d_in[5],   // b2 [1]
        (float*)d_out);          // out [2048,64]
}